// round 6
// baseline (speedup 1.0000x reference)
#include <cuda_runtime.h>
#include <cuda_bf16.h>
#include <math.h>

// Problem constants
#define T_TOK 8192      // B*S
#define DDIM  2048
#define HDIM  2816
#define NEXP  8
#define CAP   1024      // per-expert capacity = T/E

// ---------------- scratch (device globals; no allocation allowed) ----------
// Kernels reference these directly — no cudaGetSymbolAddress on the capture path.
__device__ float g_xd[(size_t)T_TOK * DDIM];    // dispatched tokens  [E*C, D]
__device__ float g_h1[(size_t)T_TOK * HDIM];    // h1 / shared s1     [T, H]
__device__ float g_h3[(size_t)T_TOK * HDIM];    // h3 / shared s3     [T, H]
__device__ float g_oe[(size_t)T_TOK * DDIM];    // expert outputs     [E*C, D]
__device__ int   g_eidx[T_TOK];
__device__ float g_gate[T_TOK];
__device__ int   g_flat[T_TOK];
__device__ float g_gateK[T_TOK];                // gate * keep

// ---------------- routing: logits -> softmax gate + argmax ----------------
__global__ void route_kernel(const float* __restrict__ x, const float* __restrict__ Wg) {
    int warp = threadIdx.x >> 5;
    int lane = threadIdx.x & 31;
    int t = blockIdx.x * 8 + warp;
    if (t >= T_TOK) return;
    const float* xr = x + (long)t * DDIM;
    float acc[NEXP];
#pragma unroll
    for (int e = 0; e < NEXP; e++) acc[e] = 0.0f;
    for (int d = lane; d < DDIM; d += 32) {
        float xv = xr[d];
        float4 w0 = *(const float4*)(Wg + (long)d * NEXP);
        float4 w1 = *(const float4*)(Wg + (long)d * NEXP + 4);
        acc[0] += xv * w0.x; acc[1] += xv * w0.y;
        acc[2] += xv * w0.z; acc[3] += xv * w0.w;
        acc[4] += xv * w1.x; acc[5] += xv * w1.y;
        acc[6] += xv * w1.z; acc[7] += xv * w1.w;
    }
#pragma unroll
    for (int off = 16; off > 0; off >>= 1) {
#pragma unroll
        for (int e = 0; e < NEXP; e++)
            acc[e] += __shfl_xor_sync(0xffffffffu, acc[e], off);
    }
    if (lane == 0) {
        float m = acc[0]; int bi = 0;
#pragma unroll
        for (int e = 1; e < NEXP; e++) {
            if (acc[e] > m) { m = acc[e]; bi = e; }   // first-max wins (argmax semantics)
        }
        float s = 0.0f;
#pragma unroll
        for (int e = 0; e < NEXP; e++) s += expf(acc[e] - m);
        g_eidx[t] = bi;
        g_gate[t] = 1.0f / s;   // probs[argmax] = exp(0)/sum
    }
}

// ---------------- scan: per-expert position in token order -----------------
// 1 block, 1024 threads, 8 tokens/thread. Hillis-Steele over 8-vector counts.
__global__ void scan_kernel() {
    __shared__ int sc[1024][NEXP];
    int tid = threadIdx.x;
    int cnt[NEXP];
#pragma unroll
    for (int e = 0; e < NEXP; e++) cnt[e] = 0;
    int myexp[8], mypos[8];
    for (int i = 0; i < 8; i++) {
        int e = g_eidx[tid * 8 + i];
        myexp[i] = e;
        mypos[i] = cnt[e];
        cnt[e] += 1;
    }
#pragma unroll
    for (int e = 0; e < NEXP; e++) sc[tid][e] = cnt[e];
    __syncthreads();
    for (int off = 1; off < 1024; off <<= 1) {
        int v[NEXP];
        if (tid >= off) {
#pragma unroll
            for (int e = 0; e < NEXP; e++) v[e] = sc[tid - off][e];
        }
        __syncthreads();
        if (tid >= off) {
#pragma unroll
            for (int e = 0; e < NEXP; e++) sc[tid][e] += v[e];
        }
        __syncthreads();
    }
    int base[NEXP];
#pragma unroll
    for (int e = 0; e < NEXP; e++) base[e] = sc[tid][e] - cnt[e];  // exclusive
    for (int i = 0; i < 8; i++) {
        int tt = tid * 8 + i;
        int pos = base[myexp[i]] + mypos[i];
        bool keep = pos < CAP;
        g_flat[tt]  = keep ? (myexp[i] * CAP + pos) : (NEXP * CAP);
        g_gateK[tt] = keep ? g_gate[tt] : 0.0f;
    }
}

// ---------------- dispatch --------------------------------------------------
__global__ void zero_xd_kernel() {
    long i = (long)blockIdx.x * blockDim.x + threadIdx.x;
    const long n4 = (long)T_TOK * DDIM / 4;
    if (i < n4) ((float4*)g_xd)[i] = make_float4(0.f, 0.f, 0.f, 0.f);
}

__global__ void scatter_kernel(const float* __restrict__ x) {
    int t = blockIdx.x;
    int f = g_flat[t];
    if (f >= NEXP * CAP) return;
    const float4* src = (const float4*)(x + (long)t * DDIM);
    float4*       dst = (float4*)(g_xd + (long)f * DDIM);
    for (int i = threadIdx.x; i < DDIM / 4; i += blockDim.x) dst[i] = src[i];
}

// ---------------- SGEMM 128x128x8, 256 threads, 8x8 microtile --------------
// Row-major: C[M,N] = A[M,K] @ B[K,N]. Batched via blockIdx.z + strides.
#define BM 128
#define BN 128
#define BK 8
#define TM 8
#define TN 8

__global__ __launch_bounds__(256, 2)
void sgemm_kernel(const float* __restrict__ A, const float* __restrict__ B,
                  float* __restrict__ C, int M, int N, int K,
                  long sA, long sB, long sC) {
    A += (long)blockIdx.z * sA;
    B += (long)blockIdx.z * sB;
    C += (long)blockIdx.z * sC;

    __shared__ float As[2][BK][BM];
    __shared__ float Bs[2][BK][BN];

    const int tid = threadIdx.x;
    const int bx = blockIdx.x;   // N tile
    const int by = blockIdx.y;   // M tile

    // A tile load: 128 rows x 8 k -> 256 float4 (1/thread), stored transposed
    const int aRow = tid >> 1;          // 0..127
    const int aCol = (tid & 1) * 4;     // 0 or 4
    // B tile load: 8 rows x 128 n -> 256 float4 (1/thread)
    const int bRow = tid >> 5;          // 0..7
    const int bCol = (tid & 31) * 4;    // 0..124

    const float* Aptr = A + ((long)(by * BM + aRow)) * K + aCol;
    const float* Bptr = B + (long)bRow * N + (long)bx * BN + bCol;

    const int tx = tid & 15;
    const int ty = tid >> 4;

    float acc[TM][TN];
#pragma unroll
    for (int i = 0; i < TM; i++)
#pragma unroll
        for (int j = 0; j < TN; j++) acc[i][j] = 0.0f;

    const int nTiles = K / BK;

    // prologue
    float4 a4 = *(const float4*)Aptr;
    float4 b4 = *(const float4*)Bptr;
    As[0][aCol + 0][aRow] = a4.x;
    As[0][aCol + 1][aRow] = a4.y;
    As[0][aCol + 2][aRow] = a4.z;
    As[0][aCol + 3][aRow] = a4.w;
    *(float4*)&Bs[0][bRow][bCol] = b4;
    __syncthreads();

    for (int t = 0; t < nTiles; t++) {
        const int cur = t & 1;
        const int nxt = cur ^ 1;
        if (t + 1 < nTiles) {
            a4 = *(const float4*)(Aptr + (long)(t + 1) * BK);
            b4 = *(const float4*)(Bptr + (long)(t + 1) * BK * N);
        }
#pragma unroll
        for (int k = 0; k < BK; k++) {
            float ar[TM], br[TN];
            *(float4*)&ar[0] = *(const float4*)&As[cur][k][ty * TM];
            *(float4*)&ar[4] = *(const float4*)&As[cur][k][ty * TM + 4];
            *(float4*)&br[0] = *(const float4*)&Bs[cur][k][tx * TN];
            *(float4*)&br[4] = *(const float4*)&Bs[cur][k][tx * TN + 4];
#pragma unroll
            for (int i = 0; i < TM; i++)
#pragma unroll
                for (int j = 0; j < TN; j++)
                    acc[i][j] += ar[i] * br[j];
        }
        if (t + 1 < nTiles) {
            As[nxt][aCol + 0][aRow] = a4.x;
            As[nxt][aCol + 1][aRow] = a4.y;
            As[nxt][aCol + 2][aRow] = a4.z;
            As[nxt][aCol + 3][aRow] = a4.w;
            *(float4*)&Bs[nxt][bRow][bCol] = b4;
            __syncthreads();
        }
    }

    // epilogue
    float* Cp = C + ((long)(by * BM + ty * TM)) * N + (long)bx * BN + tx * TN;
#pragma unroll
    for (int i = 0; i < TM; i++) {
        *(float4*)(Cp + (long)i * N)     = *(float4*)&acc[i][0];
        *(float4*)(Cp + (long)i * N + 4) = *(float4*)&acc[i][4];
    }
}

// ---------------- SwiGLU elementwise: h1 = silu(h1) * h3 -------------------
__global__ void swiglu_kernel() {
    long i = (long)blockIdx.x * blockDim.x + threadIdx.x;
    const long n4 = (long)T_TOK * HDIM / 4;
    if (i >= n4) return;
    float4 a = ((float4*)g_h1)[i];
    float4 b = ((const float4*)g_h3)[i];
    a.x = (a.x / (1.0f + expf(-a.x))) * b.x;
    a.y = (a.y / (1.0f + expf(-a.y))) * b.y;
    a.z = (a.z / (1.0f + expf(-a.z))) * b.z;
    a.w = (a.w / (1.0f + expf(-a.w))) * b.w;
    ((float4*)g_h1)[i] = a;
}

// ---------------- combine: out[t] += gateK[t] * oe[flat[t]] ----------------
__global__ void combine_kernel(float* __restrict__ out) {
    int t = blockIdx.x;
    float g = g_gateK[t];
    if (g == 0.0f) return;   // dropped (gate itself is always >= 1/E > 0)
    int f = g_flat[t];
    const float4* src = (const float4*)(g_oe + (long)f * DDIM);
    float4*       dst = (float4*)(out + (long)t * DDIM);
    for (int i = threadIdx.x; i < DDIM / 4; i += blockDim.x) {
        float4 a = dst[i];
        float4 b = src[i];
        a.x += g * b.x; a.y += g * b.y; a.z += g * b.z; a.w += g * b.w;
        dst[i] = a;
    }
}

// Device-global pointer accessors for the GEMM launches (host needs raw addresses
// only for kernel *arguments*; use small passthrough kernels instead? No — we can
// pass the globals via device symbols resolved at launch time with kernels that
// take no scratch pointers. Simplest: dedicated GEMM entry points binding the
// right global buffers as constants.)

__global__ __launch_bounds__(256, 2)
void sgemm_shared1(const float* __restrict__ A, const float* __restrict__ Bw, int which) {
    // thin wrappers below instead
}

// ---- GEMM wrappers binding device-global scratch (avoid host symbol lookup) ----
// Each wrapper simply forwards to the generic body via inlined call.
__device__ __forceinline__
void sgemm_body(const float* __restrict__ A, const float* __restrict__ B,
                float* __restrict__ C, int M, int N, int K,
                long sA, long sB, long sC) {
    A += (long)blockIdx.z * sA;
    B += (long)blockIdx.z * sB;
    C += (long)blockIdx.z * sC;

    __shared__ float As[2][BK][BM];
    __shared__ float Bs[2][BK][BN];

    const int tid = threadIdx.x;
    const int bx = blockIdx.x;
    const int by = blockIdx.y;

    const int aRow = tid >> 1;
    const int aCol = (tid & 1) * 4;
    const int bRow = tid >> 5;
    const int bCol = (tid & 31) * 4;

    const float* Aptr = A + ((long)(by * BM + aRow)) * K + aCol;
    const float* Bptr = B + (long)bRow * N + (long)bx * BN + bCol;

    const int tx = tid & 15;
    const int ty = tid >> 4;

    float acc[TM][TN];
#pragma unroll
    for (int i = 0; i < TM; i++)
#pragma unroll
        for (int j = 0; j < TN; j++) acc[i][j] = 0.0f;

    const int nTiles = K / BK;

    float4 a4 = *(const float4*)Aptr;
    float4 b4 = *(const float4*)Bptr;
    As[0][aCol + 0][aRow] = a4.x;
    As[0][aCol + 1][aRow] = a4.y;
    As[0][aCol + 2][aRow] = a4.z;
    As[0][aCol + 3][aRow] = a4.w;
    *(float4*)&Bs[0][bRow][bCol] = b4;
    __syncthreads();

    for (int t = 0; t < nTiles; t++) {
        const int cur = t & 1;
        const int nxt = cur ^ 1;
        if (t + 1 < nTiles) {
            a4 = *(const float4*)(Aptr + (long)(t + 1) * BK);
            b4 = *(const float4*)(Bptr + (long)(t + 1) * BK * N);
        }
#pragma unroll
        for (int k = 0; k < BK; k++) {
            float ar[TM], br[TN];
            *(float4*)&ar[0] = *(const float4*)&As[cur][k][ty * TM];
            *(float4*)&ar[4] = *(const float4*)&As[cur][k][ty * TM + 4];
            *(float4*)&br[0] = *(const float4*)&Bs[cur][k][tx * TN];
            *(float4*)&br[4] = *(const float4*)&Bs[cur][k][tx * TN + 4];
#pragma unroll
            for (int i = 0; i < TM; i++)
#pragma unroll
                for (int j = 0; j < TN; j++)
                    acc[i][j] += ar[i] * br[j];
        }
        if (t + 1 < nTiles) {
            As[nxt][aCol + 0][aRow] = a4.x;
            As[nxt][aCol + 1][aRow] = a4.y;
            As[nxt][aCol + 2][aRow] = a4.z;
            As[nxt][aCol + 3][aRow] = a4.w;
            *(float4*)&Bs[nxt][bRow][bCol] = b4;
            __syncthreads();
        }
    }

    float* Cp = C + ((long)(by * BM + ty * TM)) * N + (long)bx * BN + tx * TN;
#pragma unroll
    for (int i = 0; i < TM; i++) {
        *(float4*)(Cp + (long)i * N)     = *(float4*)&acc[i][0];
        *(float4*)(Cp + (long)i * N + 4) = *(float4*)&acc[i][4];
    }
}

// shared expert: h1 = x @ sw1
__global__ __launch_bounds__(256, 2)
void gemm_s1(const float* __restrict__ x, const float* __restrict__ sw1) {
    sgemm_body(x, sw1, g_h1, T_TOK, HDIM, DDIM, 0, 0, 0);
}
// shared expert: h3 = x @ sw3
__global__ __launch_bounds__(256, 2)
void gemm_s3(const float* __restrict__ x, const float* __restrict__ sw3) {
    sgemm_body(x, sw3, g_h3, T_TOK, HDIM, DDIM, 0, 0, 0);
}
// shared expert: out = h1 @ sw2   (writes d_out directly)
__global__ __launch_bounds__(256, 2)
void gemm_s2(const float* __restrict__ sw2, float* __restrict__ out) {
    sgemm_body(g_h1, sw2, out, T_TOK, DDIM, HDIM, 0, 0, 0);
}
// routed experts: h1 = xd @ W1   (batched over E)
__global__ __launch_bounds__(256, 2)
void gemm_e1(const float* __restrict__ W1) {
    sgemm_body(g_xd, W1, g_h1, CAP, HDIM, DDIM,
               (long)CAP * DDIM, (long)DDIM * HDIM, (long)CAP * HDIM);
}
// routed experts: h3 = xd @ W3
__global__ __launch_bounds__(256, 2)
void gemm_e3(const float* __restrict__ W3) {
    sgemm_body(g_xd, W3, g_h3, CAP, HDIM, DDIM,
               (long)CAP * DDIM, (long)DDIM * HDIM, (long)CAP * HDIM);
}
// routed experts: oe = h1 @ W2
__global__ __launch_bounds__(256, 2)
void gemm_e2(const float* __restrict__ W2) {
    sgemm_body(g_h1, W2, g_oe, CAP, DDIM, HDIM,
               (long)CAP * HDIM, (long)HDIM * DDIM, (long)CAP * DDIM);
}

// ---------------- launch ----------------------------------------------------
extern "C" void kernel_launch(void* const* d_in, const int* in_sizes, int n_in,
                              void* d_out, int out_size) {
    const float* x   = (const float*)d_in[0];
    const float* Wg  = (const float*)d_in[1];
    const float* W1  = (const float*)d_in[2];
    const float* W3  = (const float*)d_in[3];
    const float* W2  = (const float*)d_in[4];
    const float* sw1 = (const float*)d_in[5];
    const float* sw3 = (const float*)d_in[6];
    const float* sw2 = (const float*)d_in[7];
    float* out = (float*)d_out;

    // routing + dispatch
    route_kernel<<<T_TOK / 8, 256>>>(x, Wg);
    scan_kernel<<<1, 1024>>>();
    {
        long n4 = (long)T_TOK * DDIM / 4;
        zero_xd_kernel<<<(unsigned)((n4 + 255) / 256), 256>>>();
    }
    scatter_kernel<<<T_TOK, 256>>>(x);

    // ---- shared expert first (h-buffers then reused by routed experts) ----
    gemm_s1<<<dim3(HDIM / BN, T_TOK / BM, 1), 256>>>(x, sw1);
    gemm_s3<<<dim3(HDIM / BN, T_TOK / BM, 1), 256>>>(x, sw3);
    {
        long n4 = (long)T_TOK * HDIM / 4;
        swiglu_kernel<<<(unsigned)((n4 + 255) / 256), 256>>>();
    }
    gemm_s2<<<dim3(DDIM / BN, T_TOK / BM, 1), 256>>>(sw2, out);

    // ---- routed experts (batched over E via blockIdx.z) ----
    gemm_e1<<<dim3(HDIM / BN, CAP / BM, NEXP), 256>>>(W1);
    gemm_e3<<<dim3(HDIM / BN, CAP / BM, NEXP), 256>>>(W3);
    {
        long n4 = (long)T_TOK * HDIM / 4;
        swiglu_kernel<<<(unsigned)((n4 + 255) / 256), 256>>>();
    }
    gemm_e2<<<dim3(DDIM / BN, CAP / BM, NEXP), 256>>>(W2);

    // gather + gated add into out
    combine_kernel<<<T_TOK, 256>>>(out);
}

// round 10
// speedup vs baseline: 2.9719x; 2.9719x over previous
#include <cuda_runtime.h>
#include <cuda_bf16.h>
#include <math.h>
#include <stdint.h>

// Problem constants
#define T_TOK 8192      // B*S
#define DDIM  2048
#define HDIM  2816
#define NEXP  8
#define CAP   1024      // per-expert capacity = T/E

// ======================= device scratch (no allocs allowed) =================
__device__ float g_h1[(size_t)T_TOK * HDIM];    // GEMM1 out  [T,H] / [E,C,H]
__device__ float g_h3[(size_t)T_TOK * HDIM];    // GEMM3 out
__device__ float g_oe[(size_t)T_TOK * DDIM];    // expert out [E*C, D]
// bf16 hi/lo activation pairs
__device__ __nv_bfloat16 g_xh [(size_t)T_TOK * DDIM];
__device__ __nv_bfloat16 g_xl [(size_t)T_TOK * DDIM];
__device__ __nv_bfloat16 g_xdh[(size_t)T_TOK * DDIM];
__device__ __nv_bfloat16 g_xdl[(size_t)T_TOK * DDIM];
__device__ __nv_bfloat16 g_hh [(size_t)T_TOK * HDIM];
__device__ __nv_bfloat16 g_hl [(size_t)T_TOK * HDIM];
// bf16 hi/lo transposed weights: B stored [N,K] K-major
__device__ __nv_bfloat16 g_w1h[(size_t)NEXP * HDIM * DDIM];
__device__ __nv_bfloat16 g_w1l[(size_t)NEXP * HDIM * DDIM];
__device__ __nv_bfloat16 g_w3h[(size_t)NEXP * HDIM * DDIM];
__device__ __nv_bfloat16 g_w3l[(size_t)NEXP * HDIM * DDIM];
__device__ __nv_bfloat16 g_w2h[(size_t)NEXP * DDIM * HDIM];
__device__ __nv_bfloat16 g_w2l[(size_t)NEXP * DDIM * HDIM];
__device__ __nv_bfloat16 g_s1h[(size_t)HDIM * DDIM];
__device__ __nv_bfloat16 g_s1l[(size_t)HDIM * DDIM];
__device__ __nv_bfloat16 g_s3h[(size_t)HDIM * DDIM];
__device__ __nv_bfloat16 g_s3l[(size_t)HDIM * DDIM];
__device__ __nv_bfloat16 g_s2h[(size_t)DDIM * HDIM];
__device__ __nv_bfloat16 g_s2l[(size_t)DDIM * HDIM];
// routing
__device__ int   g_eidx[T_TOK];
__device__ float g_gate[T_TOK];
__device__ int   g_flat[T_TOK];
__device__ float g_gateK[T_TOK];

// ======================= PTX helpers (base-target-legal only) ===============
__device__ __forceinline__ uint32_t smem_u32(const void* p) {
    uint32_t a;
    asm("{ .reg .u64 t; cvta.to.shared.u64 t, %1; cvt.u32.u64 %0, t; }"
        : "=r"(a) : "l"(p));
    return a;
}
__device__ __forceinline__ void cp16(uint32_t saddr, const void* g) {
    asm volatile("cp.async.cg.shared.global [%0], [%1], 16;"
                 :: "r"(saddr), "l"(g));
}
#define CP_COMMIT() asm volatile("cp.async.commit_group;" ::: "memory")
#define CP_WAIT(n)  asm volatile("cp.async.wait_group %0;" :: "n"(n) : "memory")

#define LDSM4(r, addr)                                                          \
    asm volatile("ldmatrix.sync.aligned.m8n8.x4.shared.b16 {%0,%1,%2,%3}, [%4];"\
        : "=r"((r)[0]), "=r"((r)[1]), "=r"((r)[2]), "=r"((r)[3]) : "r"(addr))

#define MMA16816(d, a, b0, b1)                                                  \
    asm volatile("mma.sync.aligned.m16n8k16.row.col.f32.bf16.bf16.f32 "         \
        "{%0,%1,%2,%3}, {%4,%5,%6,%7}, {%8,%9}, {%0,%1,%2,%3};"                 \
        : "+f"((d)[0]), "+f"((d)[1]), "+f"((d)[2]), "+f"((d)[3])                \
        : "r"((a)[0]), "r"((a)[1]), "r"((a)[2]), "r"((a)[3]), "r"(b0), "r"(b1))

// smem tile addressing: [128 rows][32 bf16] = 64B/row, XOR-swizzled 16B units
__device__ __forceinline__ uint32_t soff(int row, int kcol) {
    return (uint32_t)(row * 64 + (((kcol >> 3) ^ ((row >> 1) & 3)) << 4));
}

// ======================= bf16 split helper ==================================
__device__ __forceinline__ void split2(float a, float b,
                                       __nv_bfloat162& h2, __nv_bfloat162& l2) {
    __nv_bfloat16 ha = __float2bfloat16_rn(a);
    __nv_bfloat16 hb = __float2bfloat16_rn(b);
    __nv_bfloat16 la = __float2bfloat16_rn(a - __bfloat162float(ha));
    __nv_bfloat16 lb = __float2bfloat16_rn(b - __bfloat162float(hb));
    h2 = __halves2bfloat162(ha, hb);
    l2 = __halves2bfloat162(la, lb);
}

// ======================= routing ============================================
__global__ void route_kernel(const float* __restrict__ x, const float* __restrict__ Wg) {
    int warp = threadIdx.x >> 5;
    int lane = threadIdx.x & 31;
    int t = blockIdx.x * 8 + warp;
    if (t >= T_TOK) return;
    const float* xr = x + (long)t * DDIM;
    float acc[NEXP];
#pragma unroll
    for (int e = 0; e < NEXP; e++) acc[e] = 0.0f;
    for (int d = lane; d < DDIM; d += 32) {
        float xv = xr[d];
        float4 w0 = *(const float4*)(Wg + (long)d * NEXP);
        float4 w1 = *(const float4*)(Wg + (long)d * NEXP + 4);
        acc[0] += xv * w0.x; acc[1] += xv * w0.y;
        acc[2] += xv * w0.z; acc[3] += xv * w0.w;
        acc[4] += xv * w1.x; acc[5] += xv * w1.y;
        acc[6] += xv * w1.z; acc[7] += xv * w1.w;
    }
#pragma unroll
    for (int off = 16; off > 0; off >>= 1)
#pragma unroll
        for (int e = 0; e < NEXP; e++)
            acc[e] += __shfl_xor_sync(0xffffffffu, acc[e], off);
    if (lane == 0) {
        float m = acc[0]; int bi = 0;
#pragma unroll
        for (int e = 1; e < NEXP; e++)
            if (acc[e] > m) { m = acc[e]; bi = e; }
        float s = 0.0f;
#pragma unroll
        for (int e = 0; e < NEXP; e++) s += expf(acc[e] - m);
        g_eidx[t] = bi;
        g_gate[t] = 1.0f / s;
    }
}

__global__ void scan_kernel() {
    __shared__ int sc[1024][NEXP];
    int tid = threadIdx.x;
    int cnt[NEXP];
#pragma unroll
    for (int e = 0; e < NEXP; e++) cnt[e] = 0;
    int myexp[8], mypos[8];
    for (int i = 0; i < 8; i++) {
        int e = g_eidx[tid * 8 + i];
        myexp[i] = e; mypos[i] = cnt[e]; cnt[e] += 1;
    }
#pragma unroll
    for (int e = 0; e < NEXP; e++) sc[tid][e] = cnt[e];
    __syncthreads();
    for (int off = 1; off < 1024; off <<= 1) {
        int v[NEXP];
        if (tid >= off)
#pragma unroll
            for (int e = 0; e < NEXP; e++) v[e] = sc[tid - off][e];
        __syncthreads();
        if (tid >= off)
#pragma unroll
            for (int e = 0; e < NEXP; e++) sc[tid][e] += v[e];
        __syncthreads();
    }
    int base[NEXP];
#pragma unroll
    for (int e = 0; e < NEXP; e++) base[e] = sc[tid][e] - cnt[e];
    for (int i = 0; i < 8; i++) {
        int tt = tid * 8 + i;
        int pos = base[myexp[i]] + mypos[i];
        bool keep = pos < CAP;
        g_flat[tt]  = keep ? (myexp[i] * CAP + pos) : (NEXP * CAP);
        g_gateK[tt] = keep ? g_gate[tt] : 0.0f;
    }
}

// ======================= dispatch / conversions =============================
__global__ void k_zero_xd() {
    long i = (long)blockIdx.x * blockDim.x + threadIdx.x;
    uint4 z = make_uint4(0, 0, 0, 0);
    ((uint4*)g_xdh)[i] = z;
    ((uint4*)g_xdl)[i] = z;
}

__global__ void k_scatter(const float* __restrict__ x) {
    int t = blockIdx.x;
    int f = g_flat[t];
    if (f >= NEXP * CAP) return;
    const float4* src = (const float4*)(x + (long)t * DDIM);
    __nv_bfloat162* dh = (__nv_bfloat162*)(g_xdh + (long)f * DDIM);
    __nv_bfloat162* dl = (__nv_bfloat162*)(g_xdl + (long)f * DDIM);
    for (int i = threadIdx.x; i < DDIM / 4; i += blockDim.x) {
        float4 v = src[i];
        __nv_bfloat162 h0, l0, h1, l1;
        split2(v.x, v.y, h0, l0);
        split2(v.z, v.w, h1, l1);
        dh[2 * i] = h0; dh[2 * i + 1] = h1;
        dl[2 * i] = l0; dl[2 * i + 1] = l1;
    }
}

__global__ void k_conv_x(const float* __restrict__ x) {
    long i = (long)blockIdx.x * blockDim.x + threadIdx.x;
    float4 v = ((const float4*)x)[i];
    __nv_bfloat162 h0, l0, h1, l1;
    split2(v.x, v.y, h0, l0);
    split2(v.z, v.w, h1, l1);
    ((__nv_bfloat162*)g_xh)[2 * i] = h0; ((__nv_bfloat162*)g_xh)[2 * i + 1] = h1;
    ((__nv_bfloat162*)g_xl)[2 * i] = l0; ((__nv_bfloat162*)g_xl)[2 * i + 1] = l1;
}

// transpose+split: in [z][K][N] fp32 -> out [z][N][K] bf16 hi/lo
__device__ __forceinline__ void tconv_body(const float* __restrict__ in,
                                           __nv_bfloat16* __restrict__ oh,
                                           __nv_bfloat16* __restrict__ ol,
                                           int K, int N) {
    __shared__ float t[32][33];
    long zo = (long)blockIdx.z * K * N;
    int n0 = blockIdx.x * 32, k0 = blockIdx.y * 32;
    int tx = threadIdx.x, ty = threadIdx.y;   // 32 x 8
#pragma unroll
    for (int i = 0; i < 32; i += 8)
        t[ty + i][tx] = in[zo + (long)(k0 + ty + i) * N + n0 + tx];
    __syncthreads();
#pragma unroll
    for (int i = 0; i < 32; i += 8) {
        float f = t[tx][ty + i];
        __nv_bfloat16 h = __float2bfloat16_rn(f);
        __nv_bfloat16 l = __float2bfloat16_rn(f - __bfloat162float(h));
        long o = zo + (long)(n0 + ty + i) * K + k0 + tx;
        oh[o] = h; ol[o] = l;
    }
}
__global__ void k_tc_w1(const float* in) { tconv_body(in, g_w1h, g_w1l, DDIM, HDIM); }
__global__ void k_tc_w3(const float* in) { tconv_body(in, g_w3h, g_w3l, DDIM, HDIM); }
__global__ void k_tc_w2(const float* in) { tconv_body(in, g_w2h, g_w2l, HDIM, DDIM); }
__global__ void k_tc_s1(const float* in) { tconv_body(in, g_s1h, g_s1l, DDIM, HDIM); }
__global__ void k_tc_s3(const float* in) { tconv_body(in, g_s3h, g_s3l, DDIM, HDIM); }
__global__ void k_tc_s2(const float* in) { tconv_body(in, g_s2h, g_s2l, HDIM, DDIM); }

// swiglu fused with bf16 split:  (silu(h1)*h3) -> g_hh/g_hl
__global__ void k_swiglu() {
    long i = (long)blockIdx.x * blockDim.x + threadIdx.x;
    float4 a = ((const float4*)g_h1)[i];
    float4 b = ((const float4*)g_h3)[i];
    float4 r;
    r.x = (a.x / (1.0f + expf(-a.x))) * b.x;
    r.y = (a.y / (1.0f + expf(-a.y))) * b.y;
    r.z = (a.z / (1.0f + expf(-a.z))) * b.z;
    r.w = (a.w / (1.0f + expf(-a.w))) * b.w;
    __nv_bfloat162 h0, l0, h1, l1;
    split2(r.x, r.y, h0, l0);
    split2(r.z, r.w, h1, l1);
    ((__nv_bfloat162*)g_hh)[2 * i] = h0; ((__nv_bfloat162*)g_hh)[2 * i + 1] = h1;
    ((__nv_bfloat162*)g_hl)[2 * i] = l0; ((__nv_bfloat162*)g_hl)[2 * i + 1] = l1;
}

__global__ void combine_kernel(float* __restrict__ out) {
    int t = blockIdx.x;
    float g = g_gateK[t];
    if (g == 0.0f) return;
    int f = g_flat[t];
    const float4* src = (const float4*)(g_oe + (long)f * DDIM);
    float4*       dst = (float4*)(out + (long)t * DDIM);
    for (int i = threadIdx.x; i < DDIM / 4; i += blockDim.x) {
        float4 a = dst[i], b = src[i];
        a.x += g * b.x; a.y += g * b.y; a.z += g * b.z; a.w += g * b.w;
        dst[i] = a;
    }
}

// ======================= mma.sync bf16-pair GEMM ============================
// C[M,N] fp32 = A[M,K] x B[N,K]^T via 3-product split (AhBh + AlBh + AhBl).
// CTA tile 128x128x32; 8 warps (4M x 2N), warp tile 32x64; 2-stage cp.async.
#define TILE_B   8192                 // one 128x32 bf16 tile
#define STG_B    (4 * TILE_B)         // Ah, Al, Bh, Bl
#define GEMM_SMEM (2 * STG_B)         // 65536

__device__ __forceinline__ void mma_gemm_body(
    const __nv_bfloat16* __restrict__ Ah, const __nv_bfloat16* __restrict__ Al,
    const __nv_bfloat16* __restrict__ Bh, const __nv_bfloat16* __restrict__ Bl,
    float* __restrict__ C, int K, int Nld, long sA, long sB, long sC)
{
    extern __shared__ char smem[];
    const uint32_t sb0 = smem_u32(smem);
    const int tid = threadIdx.x;
    const int wid = tid >> 5;
    const int lane = tid & 31;
    Ah += (long)blockIdx.z * sA; Al += (long)blockIdx.z * sA;
    Bh += (long)blockIdx.z * sB; Bl += (long)blockIdx.z * sB;
    C  += (long)blockIdx.z * sC;

    const int aRowBase = blockIdx.y * 128;
    const int bRowBase = blockIdx.x * 128;
    const int nK = K >> 5;

    // per-thread load slots: u in {tid, tid+256}; row = u/4, unit = u%4
    const int r0 = tid >> 2, u0 = tid & 3;
    const int r1 = (tid + 256) >> 2, u1 = (tid + 256) & 3;
    const uint32_t so0 = (uint32_t)(r0 * 64 + ((u0 ^ ((r0 >> 1) & 3)) << 4));
    const uint32_t so1 = (uint32_t)(r1 * 64 + ((u1 ^ ((r1 >> 1) & 3)) << 4));

    auto issue_loads = [&](int s) {
        const uint32_t sb = sb0 + (uint32_t)((s & 1) * STG_B);
        const long k0 = (long)s * 32;
        long ga0 = (long)(aRowBase + r0) * K + k0 + u0 * 8;
        long ga1 = (long)(aRowBase + r1) * K + k0 + u1 * 8;
        long gb0 = (long)(bRowBase + r0) * K + k0 + u0 * 8;
        long gb1 = (long)(bRowBase + r1) * K + k0 + u1 * 8;
        cp16(sb + so0,              Ah + ga0);
        cp16(sb + so1,              Ah + ga1);
        cp16(sb + TILE_B + so0,     Al + ga0);
        cp16(sb + TILE_B + so1,     Al + ga1);
        cp16(sb + 2 * TILE_B + so0, Bh + gb0);
        cp16(sb + 2 * TILE_B + so1, Bh + gb1);
        cp16(sb + 3 * TILE_B + so0, Bl + gb0);
        cp16(sb + 3 * TILE_B + so1, Bl + gb1);
    };

    float acc[2][8][4];
#pragma unroll
    for (int i = 0; i < 2; i++)
#pragma unroll
        for (int j = 0; j < 8; j++)
#pragma unroll
            for (int q = 0; q < 4; q++) acc[i][j][q] = 0.0f;

    const int wm = wid & 3;        // 0..3 -> M offset wm*32
    const int wn = wid >> 2;       // 0..1 -> N offset wn*64
    const int arow = wm * 32 + (lane & 15);
    const int akoff = ((lane >> 4) & 1) * 8;
    const int brow = wn * 64 + (lane & 7) + ((lane >> 4) & 1) * 8;
    const int bkoff = ((lane >> 3) & 1) * 8;

    issue_loads(0);
    CP_COMMIT();

    for (int s = 0; s < nK; s++) {
        if (s + 1 < nK) {
            issue_loads(s + 1);
            CP_COMMIT();
            CP_WAIT(1);
        } else {
            CP_WAIT(0);
        }
        __syncthreads();

        const uint32_t sb = sb0 + (uint32_t)((s & 1) * STG_B);
        const uint32_t sAh = sb, sAl = sb + TILE_B;
        const uint32_t sBh = sb + 2 * TILE_B, sBl = sb + 3 * TILE_B;

#pragma unroll
        for (int ks = 0; ks < 2; ks++) {
            const int kb = ks * 16;
            uint32_t ah[2][4], al[2][4];
#pragma unroll
            for (int mt = 0; mt < 2; mt++) {
                uint32_t off = soff(arow + mt * 16, kb + akoff);
                LDSM4(ah[mt], sAh + off);
                LDSM4(al[mt], sAl + off);
            }
#pragma unroll
            for (int np = 0; np < 4; np++) {
                uint32_t offb = soff(brow + np * 16, kb + bkoff);
                uint32_t bh[4], bl[4];
                LDSM4(bh, sBh + offb);
                LDSM4(bl, sBl + offb);
#pragma unroll
                for (int mt = 0; mt < 2; mt++) {
                    MMA16816(acc[mt][np * 2],     ah[mt], bh[0], bh[1]);
                    MMA16816(acc[mt][np * 2 + 1], ah[mt], bh[2], bh[3]);
                    MMA16816(acc[mt][np * 2],     al[mt], bh[0], bh[1]);
                    MMA16816(acc[mt][np * 2 + 1], al[mt], bh[2], bh[3]);
                    MMA16816(acc[mt][np * 2],     ah[mt], bl[0], bl[1]);
                    MMA16816(acc[mt][np * 2 + 1], ah[mt], bl[2], bl[3]);
                }
            }
        }
        __syncthreads();
    }

    // epilogue: fp32 direct store
#pragma unroll
    for (int mt = 0; mt < 2; mt++) {
        int row = aRowBase + wm * 32 + mt * 16 + (lane >> 2);
#pragma unroll
        for (int nt = 0; nt < 8; nt++) {
            int col = bRowBase + wn * 64 + nt * 8 + (lane & 3) * 2;
            float2 v0 = make_float2(acc[mt][nt][0], acc[mt][nt][1]);
            float2 v1 = make_float2(acc[mt][nt][2], acc[mt][nt][3]);
            *(float2*)(C + (long)row * Nld + col)       = v0;
            *(float2*)(C + (long)(row + 8) * Nld + col) = v1;
        }
    }
}

// GEMM entry points binding device-global scratch
__global__ void __launch_bounds__(256, 2) k_gemm_s1() {
    mma_gemm_body(g_xh, g_xl, g_s1h, g_s1l, g_h1, DDIM, HDIM, 0, 0, 0);
}
__global__ void __launch_bounds__(256, 2) k_gemm_s3() {
    mma_gemm_body(g_xh, g_xl, g_s3h, g_s3l, g_h3, DDIM, HDIM, 0, 0, 0);
}
__global__ void __launch_bounds__(256, 2) k_gemm_s2(float* __restrict__ out) {
    mma_gemm_body(g_hh, g_hl, g_s2h, g_s2l, out, HDIM, DDIM, 0, 0, 0);
}
__global__ void __launch_bounds__(256, 2) k_gemm_e1() {
    mma_gemm_body(g_xdh, g_xdl, g_w1h, g_w1l, g_h1, DDIM, HDIM,
                  (long)CAP * DDIM, (long)HDIM * DDIM, (long)CAP * HDIM);
}
__global__ void __launch_bounds__(256, 2) k_gemm_e3() {
    mma_gemm_body(g_xdh, g_xdl, g_w3h, g_w3l, g_h3, DDIM, HDIM,
                  (long)CAP * DDIM, (long)HDIM * DDIM, (long)CAP * HDIM);
}
__global__ void __launch_bounds__(256, 2) k_gemm_e2() {
    mma_gemm_body(g_hh, g_hl, g_w2h, g_w2l, g_oe, HDIM, DDIM,
                  (long)CAP * HDIM, (long)DDIM * HDIM, (long)CAP * DDIM);
}

// ======================= launch =============================================
extern "C" void kernel_launch(void* const* d_in, const int* in_sizes, int n_in,
                              void* d_out, int out_size) {
    const float* x   = (const float*)d_in[0];
    const float* Wg  = (const float*)d_in[1];
    const float* W1  = (const float*)d_in[2];
    const float* W3  = (const float*)d_in[3];
    const float* W2  = (const float*)d_in[4];
    const float* sw1 = (const float*)d_in[5];
    const float* sw3 = (const float*)d_in[6];
    const float* sw2 = (const float*)d_in[7];
    float* out = (float*)d_out;

    cudaFuncSetAttribute(k_gemm_s1, cudaFuncAttributeMaxDynamicSharedMemorySize, GEMM_SMEM);
    cudaFuncSetAttribute(k_gemm_s3, cudaFuncAttributeMaxDynamicSharedMemorySize, GEMM_SMEM);
    cudaFuncSetAttribute(k_gemm_s2, cudaFuncAttributeMaxDynamicSharedMemorySize, GEMM_SMEM);
    cudaFuncSetAttribute(k_gemm_e1, cudaFuncAttributeMaxDynamicSharedMemorySize, GEMM_SMEM);
    cudaFuncSetAttribute(k_gemm_e3, cudaFuncAttributeMaxDynamicSharedMemorySize, GEMM_SMEM);
    cudaFuncSetAttribute(k_gemm_e2, cudaFuncAttributeMaxDynamicSharedMemorySize, GEMM_SMEM);

    // routing + dispatch
    route_kernel<<<T_TOK / 8, 256>>>(x, Wg);
    scan_kernel<<<1, 1024>>>();
    k_zero_xd<<<4096, 512>>>();
    k_scatter<<<T_TOK, 128>>>(x);
    k_conv_x<<<16384, 256>>>(x);

    // weight transpose + bf16 split
    dim3 tb(32, 8);
    k_tc_w1<<<dim3(HDIM / 32, DDIM / 32, NEXP), tb>>>(W1);
    k_tc_w3<<<dim3(HDIM / 32, DDIM / 32, NEXP), tb>>>(W3);
    k_tc_w2<<<dim3(DDIM / 32, HDIM / 32, NEXP), tb>>>(W2);
    k_tc_s1<<<dim3(HDIM / 32, DDIM / 32, 1), tb>>>(sw1);
    k_tc_s3<<<dim3(HDIM / 32, DDIM / 32, 1), tb>>>(sw3);
    k_tc_s2<<<dim3(DDIM / 32, HDIM / 32, 1), tb>>>(sw2);

    // shared expert
    k_gemm_s1<<<dim3(HDIM / 128, T_TOK / 128, 1), 256, GEMM_SMEM>>>();
    k_gemm_s3<<<dim3(HDIM / 128, T_TOK / 128, 1), 256, GEMM_SMEM>>>();
    k_swiglu<<<(unsigned)((long)T_TOK * HDIM / 4 / 256), 256>>>();
    k_gemm_s2<<<dim3(DDIM / 128, T_TOK / 128, 1), 256, GEMM_SMEM>>>(out);

    // routed experts (batched over E)
    k_gemm_e1<<<dim3(HDIM / 128, CAP / 128, NEXP), 256, GEMM_SMEM>>>();
    k_gemm_e3<<<dim3(HDIM / 128, CAP / 128, NEXP), 256, GEMM_SMEM>>>();
    k_swiglu<<<(unsigned)((long)T_TOK * HDIM / 4 / 256), 256>>>();
    k_gemm_e2<<<dim3(DDIM / 128, CAP / 128, NEXP), 256, GEMM_SMEM>>>();

    combine_kernel<<<T_TOK, 128>>>(out);
}

// round 11
// speedup vs baseline: 3.0848x; 1.0380x over previous
#include <cuda_runtime.h>
#include <cuda_bf16.h>
#include <math.h>
#include <stdint.h>

// Problem constants
#define T_TOK 8192      // B*S
#define DDIM  2048
#define HDIM  2816
#define NEXP  8
#define CAP   1024      // per-expert capacity = T/E

// ======================= device scratch (no allocs allowed) =================
__device__ float g_h1[(size_t)T_TOK * HDIM];    // GEMM1 out  [T,H] / [E,C,H]
__device__ float g_h3[(size_t)T_TOK * HDIM];    // GEMM3 out
__device__ float g_oe[(size_t)T_TOK * DDIM];    // expert out [E*C, D]
// bf16 hi/lo activation pairs
__device__ __nv_bfloat16 g_xh [(size_t)T_TOK * DDIM];
__device__ __nv_bfloat16 g_xl [(size_t)T_TOK * DDIM];
__device__ __nv_bfloat16 g_xdh[(size_t)T_TOK * DDIM];
__device__ __nv_bfloat16 g_xdl[(size_t)T_TOK * DDIM];
__device__ __nv_bfloat16 g_hh [(size_t)T_TOK * HDIM];
__device__ __nv_bfloat16 g_hl [(size_t)T_TOK * HDIM];
// bf16 hi/lo transposed weights: B stored [N,K] K-major
__device__ __nv_bfloat16 g_w1h[(size_t)NEXP * HDIM * DDIM];
__device__ __nv_bfloat16 g_w1l[(size_t)NEXP * HDIM * DDIM];
__device__ __nv_bfloat16 g_w3h[(size_t)NEXP * HDIM * DDIM];
__device__ __nv_bfloat16 g_w3l[(size_t)NEXP * HDIM * DDIM];
__device__ __nv_bfloat16 g_w2h[(size_t)NEXP * DDIM * HDIM];
__device__ __nv_bfloat16 g_w2l[(size_t)NEXP * DDIM * HDIM];
__device__ __nv_bfloat16 g_s1h[(size_t)HDIM * DDIM];
__device__ __nv_bfloat16 g_s1l[(size_t)HDIM * DDIM];
__device__ __nv_bfloat16 g_s3h[(size_t)HDIM * DDIM];
__device__ __nv_bfloat16 g_s3l[(size_t)HDIM * DDIM];
__device__ __nv_bfloat16 g_s2h[(size_t)DDIM * HDIM];
__device__ __nv_bfloat16 g_s2l[(size_t)DDIM * HDIM];
// routing
__device__ int   g_eidx[T_TOK];
__device__ float g_gate[T_TOK];
__device__ int   g_flat[T_TOK];
__device__ float g_gateK[T_TOK];

// ======================= PTX helpers (base-target-legal only) ===============
__device__ __forceinline__ uint32_t smem_u32(const void* p) {
    uint32_t a;
    asm("{ .reg .u64 t; cvta.to.shared.u64 t, %1; cvt.u32.u64 %0, t; }"
        : "=r"(a) : "l"(p));
    return a;
}
__device__ __forceinline__ void cp16(uint32_t saddr, const void* g) {
    asm volatile("cp.async.cg.shared.global [%0], [%1], 16;"
                 :: "r"(saddr), "l"(g));
}
#define CP_COMMIT() asm volatile("cp.async.commit_group;" ::: "memory")
#define CP_WAIT(n)  asm volatile("cp.async.wait_group %0;" :: "n"(n) : "memory")

#define LDSM4(r, addr)                                                          \
    asm volatile("ldmatrix.sync.aligned.m8n8.x4.shared.b16 {%0,%1,%2,%3}, [%4];"\
        : "=r"((r)[0]), "=r"((r)[1]), "=r"((r)[2]), "=r"((r)[3]) : "r"(addr))

#define MMA16816(d, a, b0, b1)                                                  \
    asm volatile("mma.sync.aligned.m16n8k16.row.col.f32.bf16.bf16.f32 "         \
        "{%0,%1,%2,%3}, {%4,%5,%6,%7}, {%8,%9}, {%0,%1,%2,%3};"                 \
        : "+f"((d)[0]), "+f"((d)[1]), "+f"((d)[2]), "+f"((d)[3])                \
        : "r"((a)[0]), "r"((a)[1]), "r"((a)[2]), "r"((a)[3]), "r"(b0), "r"(b1))

// smem tile addressing: [128 rows][32 bf16] = 64B/row, XOR-swizzled 16B units
__device__ __forceinline__ uint32_t soff(int row, int kcol) {
    return (uint32_t)(row * 64 + (((kcol >> 3) ^ ((row >> 1) & 3)) << 4));
}

// ======================= bf16 split helper ==================================
__device__ __forceinline__ void split2(float a, float b,
                                       __nv_bfloat162& h2, __nv_bfloat162& l2) {
    __nv_bfloat16 ha = __float2bfloat16_rn(a);
    __nv_bfloat16 hb = __float2bfloat16_rn(b);
    __nv_bfloat16 la = __float2bfloat16_rn(a - __bfloat162float(ha));
    __nv_bfloat16 lb = __float2bfloat16_rn(b - __bfloat162float(hb));
    h2 = __halves2bfloat162(ha, hb);
    l2 = __halves2bfloat162(la, lb);
}

// ======================= routing ============================================
__global__ void route_kernel(const float* __restrict__ x, const float* __restrict__ Wg) {
    int warp = threadIdx.x >> 5;
    int lane = threadIdx.x & 31;
    int t = blockIdx.x * 8 + warp;
    if (t >= T_TOK) return;
    const float* xr = x + (long)t * DDIM;
    float acc[NEXP];
#pragma unroll
    for (int e = 0; e < NEXP; e++) acc[e] = 0.0f;
    for (int d = lane; d < DDIM; d += 32) {
        float xv = xr[d];
        float4 w0 = *(const float4*)(Wg + (long)d * NEXP);
        float4 w1 = *(const float4*)(Wg + (long)d * NEXP + 4);
        acc[0] += xv * w0.x; acc[1] += xv * w0.y;
        acc[2] += xv * w0.z; acc[3] += xv * w0.w;
        acc[4] += xv * w1.x; acc[5] += xv * w1.y;
        acc[6] += xv * w1.z; acc[7] += xv * w1.w;
    }
#pragma unroll
    for (int off = 16; off > 0; off >>= 1)
#pragma unroll
        for (int e = 0; e < NEXP; e++)
            acc[e] += __shfl_xor_sync(0xffffffffu, acc[e], off);
    if (lane == 0) {
        float m = acc[0]; int bi = 0;
#pragma unroll
        for (int e = 1; e < NEXP; e++)
            if (acc[e] > m) { m = acc[e]; bi = e; }
        float s = 0.0f;
#pragma unroll
        for (int e = 0; e < NEXP; e++) s += expf(acc[e] - m);
        g_eidx[t] = bi;
        g_gate[t] = 1.0f / s;
    }
}

__global__ void scan_kernel() {
    __shared__ int sc[1024][NEXP];
    int tid = threadIdx.x;
    int cnt[NEXP];
#pragma unroll
    for (int e = 0; e < NEXP; e++) cnt[e] = 0;
    int myexp[8], mypos[8];
    for (int i = 0; i < 8; i++) {
        int e = g_eidx[tid * 8 + i];
        myexp[i] = e; mypos[i] = cnt[e]; cnt[e] += 1;
    }
#pragma unroll
    for (int e = 0; e < NEXP; e++) sc[tid][e] = cnt[e];
    __syncthreads();
    for (int off = 1; off < 1024; off <<= 1) {
        int v[NEXP];
        if (tid >= off)
#pragma unroll
            for (int e = 0; e < NEXP; e++) v[e] = sc[tid - off][e];
        __syncthreads();
        if (tid >= off)
#pragma unroll
            for (int e = 0; e < NEXP; e++) sc[tid][e] += v[e];
        __syncthreads();
    }
    int base[NEXP];
#pragma unroll
    for (int e = 0; e < NEXP; e++) base[e] = sc[tid][e] - cnt[e];
    for (int i = 0; i < 8; i++) {
        int tt = tid * 8 + i;
        int pos = base[myexp[i]] + mypos[i];
        bool keep = pos < CAP;
        g_flat[tt]  = keep ? (myexp[i] * CAP + pos) : (NEXP * CAP);
        g_gateK[tt] = keep ? g_gate[tt] : 0.0f;
    }
}

// ======================= dispatch / conversions =============================
// NOTE: no zeroing of g_xdh/g_xdl — unwritten rows are never read back
// (combine gathers only kept slots), so stale data there cannot affect output.
__global__ void k_scatter(const float* __restrict__ x) {
    int t = blockIdx.x;
    int f = g_flat[t];
    if (f >= NEXP * CAP) return;
    const float4* src = (const float4*)(x + (long)t * DDIM);
    __nv_bfloat162* dh = (__nv_bfloat162*)(g_xdh + (long)f * DDIM);
    __nv_bfloat162* dl = (__nv_bfloat162*)(g_xdl + (long)f * DDIM);
    for (int i = threadIdx.x; i < DDIM / 4; i += blockDim.x) {
        float4 v = src[i];
        __nv_bfloat162 h0, l0, h1, l1;
        split2(v.x, v.y, h0, l0);
        split2(v.z, v.w, h1, l1);
        dh[2 * i] = h0; dh[2 * i + 1] = h1;
        dl[2 * i] = l0; dl[2 * i + 1] = l1;
    }
}

__global__ void k_conv_x(const float* __restrict__ x) {
    long i = (long)blockIdx.x * blockDim.x + threadIdx.x;
    float4 v = ((const float4*)x)[i];
    __nv_bfloat162 h0, l0, h1, l1;
    split2(v.x, v.y, h0, l0);
    split2(v.z, v.w, h1, l1);
    ((__nv_bfloat162*)g_xh)[2 * i] = h0; ((__nv_bfloat162*)g_xh)[2 * i + 1] = h1;
    ((__nv_bfloat162*)g_xl)[2 * i] = l0; ((__nv_bfloat162*)g_xl)[2 * i + 1] = l1;
}

// transpose+split: in [z][K][N] fp32 -> out [z][N][K] bf16 hi/lo
__device__ __forceinline__ void tconv_body(const float* __restrict__ in,
                                           __nv_bfloat16* __restrict__ oh,
                                           __nv_bfloat16* __restrict__ ol,
                                           int K, int N) {
    __shared__ float t[32][33];
    long zo = (long)blockIdx.z * K * N;
    int n0 = blockIdx.x * 32, k0 = blockIdx.y * 32;
    int tx = threadIdx.x, ty = threadIdx.y;   // 32 x 8
#pragma unroll
    for (int i = 0; i < 32; i += 8)
        t[ty + i][tx] = in[zo + (long)(k0 + ty + i) * N + n0 + tx];
    __syncthreads();
#pragma unroll
    for (int i = 0; i < 32; i += 8) {
        float f = t[tx][ty + i];
        __nv_bfloat16 h = __float2bfloat16_rn(f);
        __nv_bfloat16 l = __float2bfloat16_rn(f - __bfloat162float(h));
        long o = zo + (long)(n0 + ty + i) * K + k0 + tx;
        oh[o] = h; ol[o] = l;
    }
}
__global__ void k_tc_w1(const float* in) { tconv_body(in, g_w1h, g_w1l, DDIM, HDIM); }
__global__ void k_tc_w3(const float* in) { tconv_body(in, g_w3h, g_w3l, DDIM, HDIM); }
__global__ void k_tc_w2(const float* in) { tconv_body(in, g_w2h, g_w2l, HDIM, DDIM); }
__global__ void k_tc_s1(const float* in) { tconv_body(in, g_s1h, g_s1l, DDIM, HDIM); }
__global__ void k_tc_s3(const float* in) { tconv_body(in, g_s3h, g_s3l, DDIM, HDIM); }
__global__ void k_tc_s2(const float* in) { tconv_body(in, g_s2h, g_s2l, HDIM, DDIM); }

// swiglu fused with bf16 split:  (silu(h1)*h3) -> g_hh/g_hl
__global__ void k_swiglu() {
    long i = (long)blockIdx.x * blockDim.x + threadIdx.x;
    float4 a = ((const float4*)g_h1)[i];
    float4 b = ((const float4*)g_h3)[i];
    float4 r;
    r.x = (a.x / (1.0f + expf(-a.x))) * b.x;
    r.y = (a.y / (1.0f + expf(-a.y))) * b.y;
    r.z = (a.z / (1.0f + expf(-a.z))) * b.z;
    r.w = (a.w / (1.0f + expf(-a.w))) * b.w;
    __nv_bfloat162 h0, l0, h1, l1;
    split2(r.x, r.y, h0, l0);
    split2(r.z, r.w, h1, l1);
    ((__nv_bfloat162*)g_hh)[2 * i] = h0; ((__nv_bfloat162*)g_hh)[2 * i + 1] = h1;
    ((__nv_bfloat162*)g_hl)[2 * i] = l0; ((__nv_bfloat162*)g_hl)[2 * i + 1] = l1;
}

__global__ void combine_kernel(float* __restrict__ out) {
    int t = blockIdx.x;
    float g = g_gateK[t];
    if (g == 0.0f) return;
    int f = g_flat[t];
    const float4* src = (const float4*)(g_oe + (long)f * DDIM);
    float4*       dst = (float4*)(out + (long)t * DDIM);
    for (int i = threadIdx.x; i < DDIM / 4; i += blockDim.x) {
        float4 a = dst[i], b = src[i];
        a.x += g * b.x; a.y += g * b.y; a.z += g * b.z; a.w += g * b.w;
        dst[i] = a;
    }
}

// ======================= mma.sync bf16-pair GEMM ============================
// C[M,N] fp32 = A[M,K] x B[N,K]^T via 3-product split (AhBh + AlBh + AhBl).
// CTA tile 128x128x32; 8 warps (4M x 2N), warp tile 32x64; 3-stage cp.async.
#define TILE_B   8192                 // one 128x32 bf16 tile
#define STG_B    (4 * TILE_B)         // Ah, Al, Bh, Bl
#define NSTAGE   3
#define GEMM_SMEM (NSTAGE * STG_B)    // 98304

__device__ __forceinline__ void mma_gemm_body(
    const __nv_bfloat16* __restrict__ Ah, const __nv_bfloat16* __restrict__ Al,
    const __nv_bfloat16* __restrict__ Bh, const __nv_bfloat16* __restrict__ Bl,
    float* __restrict__ C, int K, int Nld)
{
    extern __shared__ char smem[];
    const uint32_t sb0 = smem_u32(smem);
    const int tid = threadIdx.x;
    const int wid = tid >> 5;
    const int lane = tid & 31;

    const int aRowBase = blockIdx.y * 128;
    const int bRowBase = blockIdx.x * 128;
    const int nK = K >> 5;

    // per-thread load slots: u in {tid, tid+256}; row = u/4, unit = u%4
    const int r0 = tid >> 2, u0 = tid & 3;
    const int r1 = (tid + 256) >> 2, u1 = (tid + 256) & 3;
    const uint32_t so0 = (uint32_t)(r0 * 64 + ((u0 ^ ((r0 >> 1) & 3)) << 4));
    const uint32_t so1 = (uint32_t)(r1 * 64 + ((u1 ^ ((r1 >> 1) & 3)) << 4));

    auto issue_loads = [&](int s) {
        const uint32_t sb = sb0 + (uint32_t)((s % NSTAGE) * STG_B);
        const long k0 = (long)s * 32;
        long ga0 = (long)(aRowBase + r0) * K + k0 + u0 * 8;
        long ga1 = (long)(aRowBase + r1) * K + k0 + u1 * 8;
        long gb0 = (long)(bRowBase + r0) * K + k0 + u0 * 8;
        long gb1 = (long)(bRowBase + r1) * K + k0 + u1 * 8;
        cp16(sb + so0,              Ah + ga0);
        cp16(sb + so1,              Ah + ga1);
        cp16(sb + TILE_B + so0,     Al + ga0);
        cp16(sb + TILE_B + so1,     Al + ga1);
        cp16(sb + 2 * TILE_B + so0, Bh + gb0);
        cp16(sb + 2 * TILE_B + so1, Bh + gb1);
        cp16(sb + 3 * TILE_B + so0, Bl + gb0);
        cp16(sb + 3 * TILE_B + so1, Bl + gb1);
    };

    float acc[2][8][4];
#pragma unroll
    for (int i = 0; i < 2; i++)
#pragma unroll
        for (int j = 0; j < 8; j++)
#pragma unroll
            for (int q = 0; q < 4; q++) acc[i][j][q] = 0.0f;

    const int wm = wid & 3;        // 0..3 -> M offset wm*32
    const int wn = wid >> 2;       // 0..1 -> N offset wn*64
    const int arow = wm * 32 + (lane & 15);
    const int akoff = ((lane >> 4) & 1) * 8;
    const int brow = wn * 64 + (lane & 7) + ((lane >> 4) & 1) * 8;
    const int bkoff = ((lane >> 3) & 1) * 8;

    issue_loads(0);
    CP_COMMIT();
    issue_loads(1);
    CP_COMMIT();

    for (int s = 0; s < nK; s++) {
        if (s + 2 < nK) {
            issue_loads(s + 2);
            CP_COMMIT();
            CP_WAIT(2);
        } else if (s + 1 < nK) {
            CP_WAIT(1);
        } else {
            CP_WAIT(0);
        }
        __syncthreads();

        const uint32_t sb = sb0 + (uint32_t)((s % NSTAGE) * STG_B);
        const uint32_t sAh = sb, sAl = sb + TILE_B;
        const uint32_t sBh = sb + 2 * TILE_B, sBl = sb + 3 * TILE_B;

#pragma unroll
        for (int ks = 0; ks < 2; ks++) {
            const int kb = ks * 16;
            uint32_t ah[2][4], al[2][4];
#pragma unroll
            for (int mt = 0; mt < 2; mt++) {
                uint32_t off = soff(arow + mt * 16, kb + akoff);
                LDSM4(ah[mt], sAh + off);
                LDSM4(al[mt], sAl + off);
            }
#pragma unroll
            for (int np = 0; np < 4; np++) {
                uint32_t offb = soff(brow + np * 16, kb + bkoff);
                uint32_t bh[4], bl[4];
                LDSM4(bh, sBh + offb);
                LDSM4(bl, sBl + offb);
#pragma unroll
                for (int mt = 0; mt < 2; mt++) {
                    MMA16816(acc[mt][np * 2],     ah[mt], bh[0], bh[1]);
                    MMA16816(acc[mt][np * 2 + 1], ah[mt], bh[2], bh[3]);
                    MMA16816(acc[mt][np * 2],     al[mt], bh[0], bh[1]);
                    MMA16816(acc[mt][np * 2 + 1], al[mt], bh[2], bh[3]);
                    MMA16816(acc[mt][np * 2],     ah[mt], bl[0], bl[1]);
                    MMA16816(acc[mt][np * 2 + 1], ah[mt], bl[2], bl[3]);
                }
            }
        }
        __syncthreads();
    }

    // epilogue: fp32 direct store
#pragma unroll
    for (int mt = 0; mt < 2; mt++) {
        int row = aRowBase + wm * 32 + mt * 16 + (lane >> 2);
#pragma unroll
        for (int nt = 0; nt < 8; nt++) {
            int col = bRowBase + wn * 64 + nt * 8 + (lane & 3) * 2;
            float2 v0 = make_float2(acc[mt][nt][0], acc[mt][nt][1]);
            float2 v1 = make_float2(acc[mt][nt][2], acc[mt][nt][3]);
            *(float2*)(C + (long)row * Nld + col)       = v0;
            *(float2*)(C + (long)(row + 8) * Nld + col) = v1;
        }
    }
}

// ---- GEMM entry points (merged launches via blockIdx.z selection) ----------
// shared expert GEMM1+GEMM3 merged: z=0 -> (s1 -> h1), z=1 -> (s3 -> h3)
__global__ void __launch_bounds__(256, 2) k_gemm_s13() {
    const bool w3 = (blockIdx.z != 0);
    mma_gemm_body(g_xh, g_xl,
                  w3 ? g_s3h : g_s1h, w3 ? g_s3l : g_s1l,
                  w3 ? g_h3 : g_h1, DDIM, HDIM);
}
__global__ void __launch_bounds__(256, 2) k_gemm_s2(float* __restrict__ out) {
    mma_gemm_body(g_hh, g_hl, g_s2h, g_s2l, out, HDIM, DDIM);
}
// routed experts GEMM1+GEMM3 merged: z = expert + which*8
__global__ void __launch_bounds__(256, 2) k_gemm_e13() {
    const int e = blockIdx.z & 7;
    const bool w3 = (blockIdx.z >> 3) != 0;
    mma_gemm_body(g_xdh + (long)e * CAP * DDIM, g_xdl + (long)e * CAP * DDIM,
                  (w3 ? g_w3h : g_w1h) + (long)e * HDIM * DDIM,
                  (w3 ? g_w3l : g_w1l) + (long)e * HDIM * DDIM,
                  (w3 ? g_h3 : g_h1) + (long)e * CAP * HDIM, DDIM, HDIM);
}
__global__ void __launch_bounds__(256, 2) k_gemm_e2() {
    const int e = blockIdx.z;
    mma_gemm_body(g_hh + (long)e * CAP * HDIM, g_hl + (long)e * CAP * HDIM,
                  g_w2h + (long)e * DDIM * HDIM, g_w2l + (long)e * DDIM * HDIM,
                  g_oe + (long)e * CAP * DDIM, HDIM, DDIM);
}

// ======================= launch =============================================
extern "C" void kernel_launch(void* const* d_in, const int* in_sizes, int n_in,
                              void* d_out, int out_size) {
    const float* x   = (const float*)d_in[0];
    const float* Wg  = (const float*)d_in[1];
    const float* W1  = (const float*)d_in[2];
    const float* W3  = (const float*)d_in[3];
    const float* W2  = (const float*)d_in[4];
    const float* sw1 = (const float*)d_in[5];
    const float* sw3 = (const float*)d_in[6];
    const float* sw2 = (const float*)d_in[7];
    float* out = (float*)d_out;

    cudaFuncSetAttribute(k_gemm_s13, cudaFuncAttributeMaxDynamicSharedMemorySize, GEMM_SMEM);
    cudaFuncSetAttribute(k_gemm_s2,  cudaFuncAttributeMaxDynamicSharedMemorySize, GEMM_SMEM);
    cudaFuncSetAttribute(k_gemm_e13, cudaFuncAttributeMaxDynamicSharedMemorySize, GEMM_SMEM);
    cudaFuncSetAttribute(k_gemm_e2,  cudaFuncAttributeMaxDynamicSharedMemorySize, GEMM_SMEM);

    dim3 tb(32, 8);

    // Ordered so launch index 5 (ncu -s 5 -c 1 capture slot) is a GEMM.
    k_conv_x<<<16384, 256>>>(x);                                   // 0
    k_tc_s1<<<dim3(HDIM / 32, DDIM / 32, 1), tb>>>(sw1);           // 1
    k_tc_s3<<<dim3(HDIM / 32, DDIM / 32, 1), tb>>>(sw3);           // 2
    k_tc_s2<<<dim3(DDIM / 32, HDIM / 32, 1), tb>>>(sw2);           // 3
    route_kernel<<<T_TOK / 8, 256>>>(x, Wg);                       // 4
    k_gemm_s13<<<dim3(HDIM / 128, T_TOK / 128, 2), 256, GEMM_SMEM>>>();   // 5 <- profiled
    scan_kernel<<<1, 1024>>>();                                    // 6
    k_scatter<<<T_TOK, 128>>>(x);                                  // 7
    k_tc_w1<<<dim3(HDIM / 32, DDIM / 32, NEXP), tb>>>(W1);         // 8
    k_tc_w3<<<dim3(HDIM / 32, DDIM / 32, NEXP), tb>>>(W3);         // 9
    k_tc_w2<<<dim3(DDIM / 32, HDIM / 32, NEXP), tb>>>(W2);         // 10
    k_swiglu<<<(unsigned)((long)T_TOK * HDIM / 4 / 256), 256>>>(); // 11 (shared h)
    k_gemm_s2<<<dim3(DDIM / 128, T_TOK / 128, 1), 256, GEMM_SMEM>>>(out); // 12
    k_gemm_e13<<<dim3(HDIM / 128, CAP / 128, 2 * NEXP), 256, GEMM_SMEM>>>();  // 13
    k_swiglu<<<(unsigned)((long)T_TOK * HDIM / 4 / 256), 256>>>(); // 14 (expert h)
    k_gemm_e2<<<dim3(DDIM / 128, CAP / 128, NEXP), 256, GEMM_SMEM>>>();   // 15
    combine_kernel<<<T_TOK, 128>>>(out);                           // 16
}